// round 2
// baseline (speedup 1.0000x reference)
#include <cuda_runtime.h>

// Problem constants
#define BB   32
#define CC   256
#define GG   4
#define CG   64
#define HH   56
#define WW   56
#define OHh  28
#define OWw  28
#define HWp  (HH*WW)      // 3136
#define OHWp (OHh*OWw)    // 784
#define CNTp (BB*OHWp)    // 25088
#define BN_EPS 1e-5

// ---------------- scratch (device globals; no allocation allowed) ----------------
__device__ unsigned long long g_bits1[BB*GG*HWp];    // packed sign(x): [n][g][h][w], 3.2 MB
__device__ unsigned long long g_bits2[BB*OHWp*4];    // packed sign(x1): [n][p][word], 0.8 MB
__device__ unsigned long long g_w1b[CC*9];           // packed sign(w1): [oc][tap]
__device__ unsigned long long g_w2b[CC*4];           // packed sign(w2): [oc][word]
__device__ short  g_y1[BB*CC*OHWp];                  // conv1 raw int outputs, 12.8 MB
__device__ short  g_y2[BB*CC*OHWp];                  // conv2 raw int outputs, 12.8 MB
__device__ float  g_mp[BB*CC*OHWp];                  // maxpool shortcut, 25.7 MB
__device__ float  g_x1[BB*CC*OHWp];                  // stage-1 output, 25.7 MB
__device__ long long g_sum1[CC], g_sq1[CC], g_sum2[CC], g_sq2[CC];
__device__ float g_scale1[CC], g_bias1[CC], g_scale2[CC], g_bias2[CC];

// ---------------- kernels ----------------

__global__ void k_zero_stats() {
    int i = threadIdx.x;  // 256 threads
    g_sum1[i] = 0; g_sq1[i] = 0; g_sum2[i] = 0; g_sq2[i] = 0;
}

// Pack sign bits of x into per-group 64-bit words. One thread per input pixel.
__global__ void k_pack_x(const float* __restrict__ x) {
    int idx = blockIdx.x * blockDim.x + threadIdx.x;
    if (idx >= BB * HWp) return;
    int n = idx / HWp, p = idx % HWp;
    const float* xp = x + (size_t)n * CC * HWp + p;
    unsigned long long m0 = 0, m1 = 0, m2 = 0, m3 = 0;
#pragma unroll 8
    for (int c = 0; c < CG; c++) {
        if (xp[(0*CG + c) * HWp] > 0.f) m0 |= 1ull << c;
        if (xp[(1*CG + c) * HWp] > 0.f) m1 |= 1ull << c;
        if (xp[(2*CG + c) * HWp] > 0.f) m2 |= 1ull << c;
        if (xp[(3*CG + c) * HWp] > 0.f) m3 |= 1ull << c;
    }
    g_bits1[(n*GG + 0) * HWp + p] = m0;
    g_bits1[(n*GG + 1) * HWp + p] = m1;
    g_bits1[(n*GG + 2) * HWp + p] = m2;
    g_bits1[(n*GG + 3) * HWp + p] = m3;
}

// Pack sign bits of both weight tensors (tiny).
__global__ void k_pack_w(const float* __restrict__ w1, const float* __restrict__ w2) {
    int tid = blockIdx.x * blockDim.x + threadIdx.x;
    if (tid < CC * 9) {
        int oc = tid / 9, t = tid % 9;
        unsigned long long m = 0;
        for (int k = 0; k < CG; k++)
            if (w1[(size_t)(oc * CG + k) * 9 + t] > 0.f) m |= 1ull << k;
        g_w1b[tid] = m;
    } else if (tid < CC * 9 + CC * 4) {
        int r = tid - CC * 9;
        int oc = r / 4, j = r % 4;
        unsigned long long m = 0;
        for (int k = 0; k < 64; k++)
            if (w2[(size_t)oc * CC + j * 64 + k] > 0.f) m |= 1ull << k;
        g_w2b[r] = m;
    }
}

// 3x3 stride-2 pad-1 maxpool of raw x. One thread per output element.
__global__ void k_maxpool(const float* __restrict__ x) {
    int idx = blockIdx.x * blockDim.x + threadIdx.x;
    if (idx >= BB * CC * OHWp) return;
    int p = idx % OHWp, nc = idx / OHWp;
    int oh = p / OWw, ow = p % OWw;
    const float* xp = x + (size_t)nc * HWp;
    int ih0 = 2 * oh - 1, iw0 = 2 * ow - 1;
    float m = -3.402823e38f;
#pragma unroll
    for (int kh = 0; kh < 3; kh++) {
        int ih = ih0 + kh;
        if ((unsigned)ih < HH) {
            const float* rp = xp + ih * WW;
#pragma unroll
            for (int kw = 0; kw < 3; kw++) {
                int iw = iw0 + kw;
                if ((unsigned)iw < WW) m = fmaxf(m, rp[iw]);
            }
        }
    }
    g_mp[idx] = m;
}

__device__ __forceinline__ int warp_red(int v) {
#pragma unroll
    for (int o = 16; o; o >>= 1) v += __shfl_down_sync(0xffffffffu, v, o);
    return v;
}

__device__ __forceinline__ void block_stats(int lsum, int lsq, long long* sumArr, long long* sqArr, int oc) {
    __shared__ int sA[8], sB[8];
    int a = warp_red(lsum), b = warp_red(lsq);
    int lane = threadIdx.x & 31, wid = threadIdx.x >> 5;
    if (lane == 0) { sA[wid] = a; sB[wid] = b; }
    __syncthreads();
    if (wid == 0) {
        int nw = blockDim.x >> 5;
        int x2 = (lane < nw) ? sA[lane] : 0;
        int y2 = (lane < nw) ? sB[lane] : 0;
        x2 = warp_red(x2); y2 = warp_red(y2);
        if (lane == 0) {
            atomicAdd((unsigned long long*)&sumArr[oc], (unsigned long long)(long long)x2);
            atomicAdd((unsigned long long*)&sqArr[oc],  (unsigned long long)(long long)y2);
        }
    }
}

// Grouped 3x3 stride-2 binary conv via XNOR+popcount. One block per (n, oc) plane.
__global__ void k_conv1() {
    int bid = blockIdx.x;
    int n = bid / CC, oc = bid % CC;
    int g = oc >> 6;
    unsigned long long wreg[9];
#pragma unroll
    for (int t = 0; t < 9; t++) wreg[t] = g_w1b[oc * 9 + t];
    const unsigned long long* bp = g_bits1 + (size_t)(n * GG + g) * HWp;
    short* yp = g_y1 + (size_t)(n * CC + oc) * OHWp;
    int lsum = 0, lsq = 0;
    for (int p = threadIdx.x; p < OHWp; p += blockDim.x) {
        int oh = p / OWw, ow = p % OWw;
        int ih0 = 2 * oh - 1, iw0 = 2 * ow - 1;
        int s = 0, nv = 0;
#pragma unroll
        for (int kh = 0; kh < 3; kh++) {
            int ih = ih0 + kh;
            if ((unsigned)ih < HH) {
                const unsigned long long* rp = bp + ih * WW;
#pragma unroll
                for (int kw = 0; kw < 3; kw++) {
                    int iw = iw0 + kw;
                    if ((unsigned)iw < WW) { s += __popcll(rp[iw] ^ wreg[kh * 3 + kw]); nv++; }
                }
            }
        }
        int val = nv * 64 - 2 * s;
        yp[p] = (short)val;
        lsum += val; lsq += val * val;
    }
    block_stats(lsum, lsq, g_sum1, g_sq1, oc);
}

__global__ void k_scalebias1(const float* __restrict__ gamma, const float* __restrict__ beta) {
    int c = threadIdx.x;
    double mu  = (double)g_sum1[c] / CNTp;
    double var = (double)g_sq1[c] / CNTp - mu * mu;
    double sc  = (double)gamma[c] / sqrt(var + BN_EPS);
    g_scale1[c] = (float)sc;
    g_bias1[c]  = (float)((double)beta[c] - mu * sc);
}

__global__ void k_scalebias2(const float* __restrict__ gamma, const float* __restrict__ beta) {
    int c = threadIdx.x;
    double mu  = (double)g_sum2[c] / CNTp;
    double var = (double)g_sq2[c] / CNTp - mu * mu;
    double sc  = (double)gamma[c] / sqrt(var + BN_EPS);
    g_scale2[c] = (float)sc;
    g_bias2[c]  = (float)((double)beta[c] - mu * sc);
}

// Apply BN1 + maxpool shortcut -> x1, and pack sign(x1) bits for conv2.
// One thread per output pixel, loops over all 256 channels (coalesced across threads).
__global__ void k_apply1() {
    __shared__ float s_sc[CC], s_bi[CC];
    int tid = threadIdx.x;
    for (int c = tid; c < CC; c += blockDim.x) { s_sc[c] = g_scale1[c]; s_bi[c] = g_bias1[c]; }
    __syncthreads();
    int idx = blockIdx.x * blockDim.x + tid;
    if (idx >= BB * OHWp) return;
    int n = idx / OHWp, p = idx % OHWp;
    size_t base = (size_t)n * CC * OHWp + p;
    unsigned long long m[4] = {0, 0, 0, 0};
#pragma unroll 4
    for (int c = 0; c < CC; c++) {
        size_t o = base + (size_t)c * OHWp;
        float y = (float)g_y1[o] * s_sc[c] + s_bi[c] + g_mp[o];
        g_x1[o] = y;
        if (y > 0.f) m[c >> 6] |= 1ull << (c & 63);
    }
#pragma unroll
    for (int j = 0; j < 4; j++) g_bits2[(size_t)idx * 4 + j] = m[j];
}

// 1x1 binary conv over 256 channels = 4 XNOR-popcount words. One block per (n, oc).
__global__ void k_conv2() {
    int bid = blockIdx.x;
    int n = bid / CC, oc = bid % CC;
    unsigned long long w0 = g_w2b[oc*4+0], w1r = g_w2b[oc*4+1];
    unsigned long long w2r = g_w2b[oc*4+2], w3 = g_w2b[oc*4+3];
    const unsigned long long* bp = g_bits2 + (size_t)n * OHWp * 4;
    short* yp = g_y2 + (size_t)(n * CC + oc) * OHWp;
    int lsum = 0, lsq = 0;
    for (int p = threadIdx.x; p < OHWp; p += blockDim.x) {
        const unsigned long long* q = bp + (size_t)p * 4;
        int s = __popcll(q[0] ^ w0) + __popcll(q[1] ^ w1r)
              + __popcll(q[2] ^ w2r) + __popcll(q[3] ^ w3);
        int val = 256 - 2 * s;
        yp[p] = (short)val;
        lsum += val; lsq += val * val;
    }
    block_stats(lsum, lsq, g_sum2, g_sq2, oc);
}

// out = bn2(y2) + x1
__global__ void k_final(float* __restrict__ out) {
    int idx = blockIdx.x * blockDim.x + threadIdx.x;
    if (idx >= BB * CC * OHWp) return;
    int c = (idx / OHWp) & (CC - 1);
    out[idx] = (float)g_y2[idx] * g_scale2[c] + g_bias2[c] + g_x1[idx];
}

// ---------------- launch ----------------
extern "C" void kernel_launch(void* const* d_in, const int* in_sizes, int n_in,
                              void* d_out, int out_size) {
    const float* x      = (const float*)d_in[0];
    const float* w1     = (const float*)d_in[1];
    const float* w2     = (const float*)d_in[2];
    const float* gamma1 = (const float*)d_in[3];
    const float* beta1  = (const float*)d_in[4];
    const float* gamma2 = (const float*)d_in[5];
    const float* beta2  = (const float*)d_in[6];
    float* out = (float*)d_out;

    k_zero_stats<<<1, 256>>>();
    k_pack_x<<<(BB * HWp + 255) / 256, 256>>>(x);
    k_pack_w<<<(CC * 9 + CC * 4 + 255) / 256, 256>>>(w1, w2);
    k_maxpool<<<(BB * CC * OHWp + 255) / 256, 256>>>(x);
    k_conv1<<<BB * CC, 256>>>();
    k_scalebias1<<<1, CC>>>(gamma1, beta1);
    k_apply1<<<(BB * OHWp) / 256, 256>>>();
    k_conv2<<<BB * CC, 256>>>();
    k_scalebias2<<<1, CC>>>(gamma2, beta2);
    k_final<<<(BB * CC * OHWp + 255) / 256, 256>>>(out);
}

// round 3
// speedup vs baseline: 1.0133x; 1.0133x over previous
#include <cuda_runtime.h>

// Problem constants
#define BB   32
#define CC   256
#define GG   4
#define CG   64
#define HH   56
#define WW   56
#define OHh  28
#define OWw  28
#define HWp  (HH*WW)      // 3136
#define OHWp (OHh*OWw)    // 784
#define CNTp (BB*OHWp)    // 25088
#define BN_EPS 1e-5

// ---------------- scratch (device globals; no allocation allowed) ----------------
__device__ unsigned long long g_bits1[BB*GG*HWp];    // packed sign(x): [n][g][h][w], 3.2 MB
__device__ unsigned long long g_bits2[BB*OHWp*4];    // packed sign(x1): [n][p][word], 0.8 MB
__device__ unsigned long long g_w1b[CC*9];           // packed sign(w1): [oc][tap]
__device__ unsigned long long g_w2b[CC*4];           // packed sign(w2): [oc][word]
__device__ short  g_y1[BB*CC*OHWp];                  // conv1 raw int outputs, 12.8 MB
__device__ short  g_y2[BB*CC*OHWp];                  // conv2 raw int outputs, 12.8 MB
__device__ float  g_mp[BB*CC*OHWp];                  // maxpool shortcut, 25.7 MB
__device__ float  g_x1[BB*CC*OHWp];                  // stage-1 output, 25.7 MB
__device__ long long g_sum1[CC], g_sq1[CC], g_sum2[CC], g_sq2[CC];
__device__ float g_scale1[CC], g_bias1[CC], g_scale2[CC], g_bias2[CC];

// ---------------- kernels ----------------

__global__ void k_zero_stats() {
    int i = threadIdx.x;  // 256 threads
    g_sum1[i] = 0; g_sq1[i] = 0; g_sum2[i] = 0; g_sq2[i] = 0;
}

// Pack sign bits of x into per-group 64-bit words. One thread per input pixel.
__global__ void k_pack_x(const float* __restrict__ x) {
    int idx = blockIdx.x * blockDim.x + threadIdx.x;
    if (idx >= BB * HWp) return;
    int n = idx / HWp, p = idx % HWp;
    const float* xp = x + (size_t)n * CC * HWp + p;
    unsigned long long m0 = 0, m1 = 0, m2 = 0, m3 = 0;
#pragma unroll 8
    for (int c = 0; c < CG; c++) {
        if (xp[(0*CG + c) * HWp] > 0.f) m0 |= 1ull << c;
        if (xp[(1*CG + c) * HWp] > 0.f) m1 |= 1ull << c;
        if (xp[(2*CG + c) * HWp] > 0.f) m2 |= 1ull << c;
        if (xp[(3*CG + c) * HWp] > 0.f) m3 |= 1ull << c;
    }
    g_bits1[(n*GG + 0) * HWp + p] = m0;
    g_bits1[(n*GG + 1) * HWp + p] = m1;
    g_bits1[(n*GG + 2) * HWp + p] = m2;
    g_bits1[(n*GG + 3) * HWp + p] = m3;
}

// Pack sign bits of both weight tensors (tiny).
__global__ void k_pack_w(const float* __restrict__ w1, const float* __restrict__ w2) {
    int tid = blockIdx.x * blockDim.x + threadIdx.x;
    if (tid < CC * 9) {
        int oc = tid / 9, t = tid % 9;
        unsigned long long m = 0;
        for (int k = 0; k < CG; k++)
            if (w1[(size_t)(oc * CG + k) * 9 + t] > 0.f) m |= 1ull << k;
        g_w1b[tid] = m;
    } else if (tid < CC * 9 + CC * 4) {
        int r = tid - CC * 9;
        int oc = r / 4, j = r % 4;
        unsigned long long m = 0;
        for (int k = 0; k < 64; k++)
            if (w2[(size_t)oc * CC + j * 64 + k] > 0.f) m |= 1ull << k;
        g_w2b[r] = m;
    }
}

// 3x3 stride-2 pad-1 maxpool of raw x. One thread per output element.
__global__ void k_maxpool(const float* __restrict__ x) {
    int idx = blockIdx.x * blockDim.x + threadIdx.x;
    if (idx >= BB * CC * OHWp) return;
    int p = idx % OHWp, nc = idx / OHWp;
    int oh = p / OWw, ow = p % OWw;
    const float* xp = x + (size_t)nc * HWp;
    int ih0 = 2 * oh - 1, iw0 = 2 * ow - 1;
    float m = -3.402823e38f;
#pragma unroll
    for (int kh = 0; kh < 3; kh++) {
        int ih = ih0 + kh;
        if ((unsigned)ih < HH) {
            const float* rp = xp + ih * WW;
#pragma unroll
            for (int kw = 0; kw < 3; kw++) {
                int iw = iw0 + kw;
                if ((unsigned)iw < WW) m = fmaxf(m, rp[iw]);
            }
        }
    }
    g_mp[idx] = m;
}

__device__ __forceinline__ int warp_red(int v) {
#pragma unroll
    for (int o = 16; o; o >>= 1) v += __shfl_down_sync(0xffffffffu, v, o);
    return v;
}

__device__ __forceinline__ void block_stats(int lsum, int lsq, long long* sumArr, long long* sqArr, int oc) {
    __shared__ int sA[8], sB[8];
    int a = warp_red(lsum), b = warp_red(lsq);
    int lane = threadIdx.x & 31, wid = threadIdx.x >> 5;
    if (lane == 0) { sA[wid] = a; sB[wid] = b; }
    __syncthreads();
    if (wid == 0) {
        int nw = blockDim.x >> 5;
        int x2 = (lane < nw) ? sA[lane] : 0;
        int y2 = (lane < nw) ? sB[lane] : 0;
        x2 = warp_red(x2); y2 = warp_red(y2);
        if (lane == 0) {
            atomicAdd((unsigned long long*)&sumArr[oc], (unsigned long long)(long long)x2);
            atomicAdd((unsigned long long*)&sqArr[oc],  (unsigned long long)(long long)y2);
        }
    }
}

// Grouped 3x3 stride-2 binary conv via XNOR+popcount. One block per (n, oc) plane.
__global__ void k_conv1() {
    int bid = blockIdx.x;
    int n = bid / CC, oc = bid % CC;
    int g = oc >> 6;
    unsigned long long wreg[9];
#pragma unroll
    for (int t = 0; t < 9; t++) wreg[t] = g_w1b[oc * 9 + t];
    const unsigned long long* bp = g_bits1 + (size_t)(n * GG + g) * HWp;
    short* yp = g_y1 + (size_t)(n * CC + oc) * OHWp;
    int lsum = 0, lsq = 0;
    for (int p = threadIdx.x; p < OHWp; p += blockDim.x) {
        int oh = p / OWw, ow = p % OWw;
        int ih0 = 2 * oh - 1, iw0 = 2 * ow - 1;
        int s = 0, nv = 0;
#pragma unroll
        for (int kh = 0; kh < 3; kh++) {
            int ih = ih0 + kh;
            if ((unsigned)ih < HH) {
                const unsigned long long* rp = bp + ih * WW;
#pragma unroll
                for (int kw = 0; kw < 3; kw++) {
                    int iw = iw0 + kw;
                    if ((unsigned)iw < WW) { s += __popcll(rp[iw] ^ wreg[kh * 3 + kw]); nv++; }
                }
            }
        }
        int val = nv * 64 - 2 * s;
        yp[p] = (short)val;
        lsum += val; lsq += val * val;
    }
    block_stats(lsum, lsq, g_sum1, g_sq1, oc);
}

__global__ void k_scalebias1(const float* __restrict__ gamma, const float* __restrict__ beta) {
    int c = threadIdx.x;
    double mu  = (double)g_sum1[c] / CNTp;
    double var = (double)g_sq1[c] / CNTp - mu * mu;
    double sc  = (double)gamma[c] / sqrt(var + BN_EPS);
    g_scale1[c] = (float)sc;
    g_bias1[c]  = (float)((double)beta[c] - mu * sc);
}

__global__ void k_scalebias2(const float* __restrict__ gamma, const float* __restrict__ beta) {
    int c = threadIdx.x;
    double mu  = (double)g_sum2[c] / CNTp;
    double var = (double)g_sq2[c] / CNTp - mu * mu;
    double sc  = (double)gamma[c] / sqrt(var + BN_EPS);
    g_scale2[c] = (float)sc;
    g_bias2[c]  = (float)((double)beta[c] - mu * sc);
}

// Apply BN1 + maxpool shortcut -> x1, and pack sign(x1) bits for conv2.
// One thread per output pixel, loops over all 256 channels (coalesced across threads).
__global__ void k_apply1() {
    __shared__ float s_sc[CC], s_bi[CC];
    int tid = threadIdx.x;
    for (int c = tid; c < CC; c += blockDim.x) { s_sc[c] = g_scale1[c]; s_bi[c] = g_bias1[c]; }
    __syncthreads();
    int idx = blockIdx.x * blockDim.x + tid;
    if (idx >= BB * OHWp) return;
    int n = idx / OHWp, p = idx % OHWp;
    size_t base = (size_t)n * CC * OHWp + p;
    unsigned long long m[4] = {0, 0, 0, 0};
#pragma unroll 4
    for (int c = 0; c < CC; c++) {
        size_t o = base + (size_t)c * OHWp;
        float y = (float)g_y1[o] * s_sc[c] + s_bi[c] + g_mp[o];
        g_x1[o] = y;
        if (y > 0.f) m[c >> 6] |= 1ull << (c & 63);
    }
#pragma unroll
    for (int j = 0; j < 4; j++) g_bits2[(size_t)idx * 4 + j] = m[j];
}

// 1x1 binary conv over 256 channels = 4 XNOR-popcount words. One block per (n, oc).
__global__ void k_conv2() {
    int bid = blockIdx.x;
    int n = bid / CC, oc = bid % CC;
    unsigned long long w0 = g_w2b[oc*4+0], w1r = g_w2b[oc*4+1];
    unsigned long long w2r = g_w2b[oc*4+2], w3 = g_w2b[oc*4+3];
    const unsigned long long* bp = g_bits2 + (size_t)n * OHWp * 4;
    short* yp = g_y2 + (size_t)(n * CC + oc) * OHWp;
    int lsum = 0, lsq = 0;
    for (int p = threadIdx.x; p < OHWp; p += blockDim.x) {
        const unsigned long long* q = bp + (size_t)p * 4;
        int s = __popcll(q[0] ^ w0) + __popcll(q[1] ^ w1r)
              + __popcll(q[2] ^ w2r) + __popcll(q[3] ^ w3);
        int val = 256 - 2 * s;
        yp[p] = (short)val;
        lsum += val; lsq += val * val;
    }
    block_stats(lsum, lsq, g_sum2, g_sq2, oc);
}

// out = bn2(y2) + x1
__global__ void k_final(float* __restrict__ out) {
    int idx = blockIdx.x * blockDim.x + threadIdx.x;
    if (idx >= BB * CC * OHWp) return;
    int c = (idx / OHWp) & (CC - 1);
    out[idx] = (float)g_y2[idx] * g_scale2[c] + g_bias2[c] + g_x1[idx];
}

// ---------------- launch ----------------
extern "C" void kernel_launch(void* const* d_in, const int* in_sizes, int n_in,
                              void* d_out, int out_size) {
    const float* x      = (const float*)d_in[0];
    const float* w1     = (const float*)d_in[1];
    const float* w2     = (const float*)d_in[2];
    const float* gamma1 = (const float*)d_in[3];
    const float* beta1  = (const float*)d_in[4];
    const float* gamma2 = (const float*)d_in[5];
    const float* beta2  = (const float*)d_in[6];
    float* out = (float*)d_out;

    k_zero_stats<<<1, 256>>>();
    k_pack_x<<<(BB * HWp + 255) / 256, 256>>>(x);
    k_pack_w<<<(CC * 9 + CC * 4 + 255) / 256, 256>>>(w1, w2);
    k_maxpool<<<(BB * CC * OHWp + 255) / 256, 256>>>(x);
    k_conv1<<<BB * CC, 256>>>();
    k_scalebias1<<<1, CC>>>(gamma1, beta1);
    k_apply1<<<(BB * OHWp) / 256, 256>>>();
    k_conv2<<<BB * CC, 256>>>();
    k_scalebias2<<<1, CC>>>(gamma2, beta2);
    k_final<<<(BB * CC * OHWp + 255) / 256, 256>>>(out);
}

// round 4
// speedup vs baseline: 1.2839x; 1.2671x over previous
#include <cuda_runtime.h>
#include <cfloat>
#include <math.h>

#define BB   32
#define CC   256
#define GG   4
#define CG   64
#define HH   56
#define WW   56
#define OH   28
#define OW   28
#define HWp  (HH*WW)      // 3136
#define OHWp (OH*OW)      // 784
#define CNT  (BB*OHWp)    // 25088
#define BN_EPS 1e-5

// ---------------- scratch (device globals; no allocation allowed) ----------------
__device__ __align__(32) unsigned long long g_bits1[BB*GG*HWp]; // packed sign(x): [n][g][p]
__device__ unsigned g_bits2u[BB*8*OHWp];                        // packed sign(x1): [n][chunk32][p]
__device__ unsigned long long g_w1b[CC*9];                      // packed sign(w1): [oc][tap]
__device__ unsigned long long g_w2b[CC*4];                      // packed sign(w2): [oc][word]
__device__ short g_y1[BB*CC*OHWp];                              // conv1 raw ints
__device__ short g_y2[BB*CC*OHWp];                              // conv2 raw ints
__device__ float g_x1[BB*CC*OHWp];                              // stage-1 output
__device__ float g_scale1[CC], g_bias1[CC], g_scale2[CC], g_bias2[CC];

// ---------------- kernels ----------------

// Pack sign(x) -> bit planes. Thread = (n, g, 4 pixels). 1 LDG.128 per 4 pixels per channel.
__global__ void k_pack_x(const float* __restrict__ x) {
    int idx = blockIdx.x * 256 + threadIdx.x;       // 32*4*784 = 100352 threads
    int p4 = idx % (HWp/4);
    int t  = idx / (HWp/4);
    int g = t & 3, n = t >> 2;
    int p = p4 * 4;
    const float* xp = x + ((size_t)(n*CC + g*CG)) * HWp + p;
    unsigned long long m0=0, m1=0, m2=0, m3=0;
#pragma unroll 16
    for (int c = 0; c < CG; c++) {
        float4 v = *(const float4*)(xp + (size_t)c * HWp);
        unsigned long long b = 1ull << c;
        if (v.x > 0.f) m0 |= b;
        if (v.y > 0.f) m1 |= b;
        if (v.z > 0.f) m2 |= b;
        if (v.w > 0.f) m3 |= b;
    }
    unsigned long long* o = g_bits1 + ((size_t)(n*GG + g)) * HWp + p;
    ulonglong2 a; a.x = m0; a.y = m1;
    ulonglong2 b2; b2.x = m2; b2.y = m3;
    *(ulonglong2*)o       = a;
    *(ulonglong2*)(o + 2) = b2;
}

// Pack sign bits of both weight tensors (tiny).
__global__ void k_pack_w(const float* __restrict__ w1, const float* __restrict__ w2) {
    int tid = blockIdx.x * blockDim.x + threadIdx.x;
    if (tid < CC * 9) {
        int oc = tid / 9, t = tid % 9;
        unsigned long long m = 0;
        for (int k = 0; k < CG; k++)
            if (w1[(size_t)(oc * CG + k) * 9 + t] > 0.f) m |= 1ull << k;
        g_w1b[tid] = m;
    } else if (tid < CC * 9 + CC * 4) {
        int r = tid - CC * 9;
        int oc = r / 4, j = r % 4;
        unsigned long long m = 0;
        for (int k = 0; k < 64; k++)
            if (w2[(size_t)oc * CC + j * 64 + k] > 0.f) m |= 1ull << k;
        g_w2b[r] = m;
    }
}

// Grouped 3x3 s2 binary conv. Block = (n, g, oc-tile of 16). Bit plane staged in smem,
// 9 words loaded once per pixel and reused across 16 output channels.
__global__ void k_conv1() {
    int b = blockIdx.x;                 // 32*4*4 = 512
    int octile = b & 3;
    int g = (b >> 2) & 3;
    int n = b >> 4;
    __shared__ unsigned long long sp[HWp];      // 25088 B
    __shared__ unsigned long long sw[16][9];
    const unsigned long long* bp = g_bits1 + (size_t)(n*GG + g) * HWp;
    for (int i = threadIdx.x; i < HWp; i += 256) sp[i] = bp[i];
    if (threadIdx.x < 144) {
        int oc = threadIdx.x / 9, t = threadIdx.x % 9;
        sw[oc][t] = g_w1b[(size_t)(g*CG + octile*16 + oc) * 9 + t];
    }
    __syncthreads();
    short* yp = g_y1 + ((size_t)n*CC + g*CG + octile*16) * OHWp;

    for (int p = threadIdx.x; p < OHWp; p += 256) {
        int oh = p / OW, ow = p - oh * OW;
        int ih0 = 2*oh - 1, iw0 = 2*ow - 1;
        unsigned long long a[9];
        if (oh > 0 && ow > 0) {      // interior: all 9 taps valid
            const unsigned long long* r = sp + ih0 * WW + iw0;
            a[0]=r[0];    a[1]=r[1];    a[2]=r[2];
            a[3]=r[WW];   a[4]=r[WW+1]; a[5]=r[WW+2];
            a[6]=r[2*WW]; a[7]=r[2*WW+1]; a[8]=r[2*WW+2];
#pragma unroll
            for (int oc = 0; oc < 16; oc++) {
                int s = 0;
#pragma unroll
                for (int t = 0; t < 9; t++) s += __popcll(a[t] ^ sw[oc][t]);
                yp[(size_t)oc*OHWp + p] = (short)(576 - 2*s);
            }
        } else {                     // boundary (top row / left col)
            bool vld[9]; int nv = 0;
#pragma unroll
            for (int t = 0; t < 9; t++) {
                int ih = ih0 + t/3, iw = iw0 + t%3;
                bool v = ((unsigned)ih < HH) & ((unsigned)iw < WW);
                vld[t] = v;
                a[t] = v ? sp[ih*WW + iw] : 0ull;
                nv += v;
            }
#pragma unroll
            for (int oc = 0; oc < 16; oc++) {
                int s = 0;
#pragma unroll
                for (int t = 0; t < 9; t++) if (vld[t]) s += __popcll(a[t] ^ sw[oc][t]);
                yp[(size_t)oc*OHWp + p] = (short)(nv*64 - 2*s);
            }
        }
    }
}

__device__ __forceinline__ int warp_red(int v) {
#pragma unroll
    for (int o = 16; o; o >>= 1) v += __shfl_down_sync(0xffffffffu, v, o);
    return v;
}

// Exact per-channel stats over int conv outputs + BN scale/bias. Block per channel, no atomics.
__global__ void k_stats_sb(int which, const float* __restrict__ gamma, const float* __restrict__ beta) {
    int c = blockIdx.x;
    const short* y = which ? g_y2 : g_y1;
    int lsum = 0, lsq = 0;
    for (int i = threadIdx.x; i < CNT; i += 256) {
        int n = i / OHWp, p = i - n * OHWp;
        int v = y[((size_t)n*CC + c) * OHWp + p];
        lsum += v; lsq += v * v;
    }
    __shared__ long long sA[8], sB[8];
    lsum = warp_red(lsum); lsq = warp_red(lsq);
    int lane = threadIdx.x & 31, w = threadIdx.x >> 5;
    if (lane == 0) { sA[w] = lsum; sB[w] = lsq; }
    __syncthreads();
    if (threadIdx.x == 0) {
        long long ts = 0, tq = 0;
#pragma unroll
        for (int i = 0; i < 8; i++) { ts += sA[i]; tq += sB[i]; }
        double mu  = (double)ts / CNT;
        double var = (double)tq / CNT - mu * mu;
        double sc  = (double)gamma[c] / sqrt(var + BN_EPS);
        if (which) { g_scale2[c] = (float)sc; g_bias2[c] = (float)((double)beta[c] - mu*sc); }
        else       { g_scale1[c] = (float)sc; g_bias1[c] = (float)((double)beta[c] - mu*sc); }
    }
}

// Fused: x1 = bn1(y1) + maxpool3x3s2(x); also packs sign(x1) for conv2.
// Block covers 32 pixels x 256 channels. Warp = one 32-channel chunk, lanes = pixels.
// Maxpool: per row one float2 load (cols 2ow,2ow+1); col 2ow-1 comes from lane-1's f.y via shfl.
__global__ void k_apply1(const float* __restrict__ x) {
    __shared__ float ssc[CC], sbi[CC];
    int tid = threadIdx.x;
    if (tid < CC) { ssc[tid] = g_scale1[tid]; sbi[tid] = g_bias1[tid]; }
    __syncthreads();
    int lp = tid & 31, chunk = tid >> 5;
    int pg = blockIdx.x * 32 + lp;               // 0 .. CNT-1
    int n = pg / OHWp, p = pg - n * OHWp;
    int oh = p / OW, ow = p - oh * OW;
    int c0 = chunk * 32;
    int ih0 = 2*oh - 1;
    size_t ybase = ((size_t)n*CC + c0) * OHWp + p;
    const float* xb = x + ((size_t)n*CC + c0) * HWp + 2*ow;
    unsigned mask = 0;
#pragma unroll 4
    for (int cl = 0; cl < 32; cl++) {
        const float* xc = xb + (size_t)cl * HWp;
        float m = -FLT_MAX;
#pragma unroll
        for (int r = 0; r < 3; r++) {
            int ih = ih0 + r;
            bool vr = (ih >= 0);                 // ih <= 55 always
            float2 f;
            if (vr) f = *(const float2*)(xc + ih * WW);
            else { f.x = -FLT_MAX; f.y = -FLT_MAX; }
            float left = __shfl_up_sync(0xffffffffu, f.y, 1);
            float hm = fmaxf(f.x, f.y);
            if (ow > 0) {
                if (lp == 0) left = vr ? xc[ih * WW - 1] : -FLT_MAX;
                hm = fmaxf(hm, left);
            }
            m = fmaxf(m, hm);
        }
        float yv = (float)g_y1[ybase + (size_t)cl*OHWp] * ssc[c0+cl] + sbi[c0+cl] + m;
        g_x1[ybase + (size_t)cl*OHWp] = yv;
        if (yv > 0.f) mask |= 1u << cl;
    }
    g_bits2u[((size_t)n*8 + chunk) * OHWp + p] = mask;   // coalesced: fixed chunk per warp
}

// 1x1 binary conv, 256 channels = 8 x 32-bit XNOR-popcount. Block = (n, oc-tile of 16),
// bits staged in smem as 8 conflict-free uint planes.
__global__ void k_conv2() {
    int b = blockIdx.x;                 // 32*16 = 512
    int octile = b & 15, n = b >> 4;
    __shared__ unsigned sp[8*OHWp];     // 25088 B
    __shared__ unsigned sw[16][8];
    const unsigned* bp = g_bits2u + (size_t)n * 8 * OHWp;
    for (int i = threadIdx.x; i < 8*OHWp; i += 256) sp[i] = bp[i];
    if (threadIdx.x < 128) {
        int oc = threadIdx.x >> 3, k = threadIdx.x & 7;
        sw[oc][k] = ((const unsigned*)g_w2b)[(octile*16 + oc)*8 + k];
    }
    __syncthreads();
    short* yp = g_y2 + ((size_t)n*CC + octile*16) * OHWp;
    for (int p = threadIdx.x; p < OHWp; p += 256) {
        unsigned q[8];
#pragma unroll
        for (int k = 0; k < 8; k++) q[k] = sp[k*OHWp + p];
#pragma unroll
        for (int oc = 0; oc < 16; oc++) {
            int s = 0;
#pragma unroll
            for (int k = 0; k < 8; k++) s += __popc(q[k] ^ sw[oc][k]);
            yp[(size_t)oc*OHWp + p] = (short)(256 - 2*s);
        }
    }
}

// out = bn2(y2) + x1, vectorized 2-wide.
__global__ void k_final(float* __restrict__ out) {
    int i = blockIdx.x * 256 + threadIdx.x;
    if (i >= BB*CC*OHWp/2) return;
    int c = (i / (OHWp/2)) & (CC - 1);
    short2 y = ((const short2*)g_y2)[i];
    float2 x1 = ((const float2*)g_x1)[i];
    float sc = g_scale2[c], bi = g_bias2[c];
    float2 o;
    o.x = (float)y.x * sc + bi + x1.x;
    o.y = (float)y.y * sc + bi + x1.y;
    ((float2*)out)[i] = o;
}

// ---------------- launch ----------------
extern "C" void kernel_launch(void* const* d_in, const int* in_sizes, int n_in,
                              void* d_out, int out_size) {
    const float* x      = (const float*)d_in[0];
    const float* w1     = (const float*)d_in[1];
    const float* w2     = (const float*)d_in[2];
    const float* gamma1 = (const float*)d_in[3];
    const float* beta1  = (const float*)d_in[4];
    const float* gamma2 = (const float*)d_in[5];
    const float* beta2  = (const float*)d_in[6];
    float* out = (float*)d_out;

    k_pack_x<<<392, 256>>>(x);
    k_pack_w<<<(CC*9 + CC*4 + 255)/256, 256>>>(w1, w2);
    k_conv1<<<512, 256>>>();
    k_stats_sb<<<CC, 256>>>(0, gamma1, beta1);
    k_apply1<<<CNT/32, 256>>>(x);
    k_conv2<<<512, 256>>>();
    k_stats_sb<<<CC, 256>>>(1, gamma2, beta2);
    k_final<<<(BB*CC*OHWp/2 + 255)/256, 256>>>(out);
}